// round 7
// baseline (speedup 1.0000x reference)
#include <cuda_runtime.h>
#include <cstdint>

#define N_NODES 50000
#define N_EDGES 1600000
#define F_DIM 32
#define H_DIM 128
#define HID 512
#define OUTD 256

// Scratch (__device__ globals = allocation-guard-legal scratch)
__device__ float g_Pdst[(size_t)N_NODES * HID];
__device__ float g_Psrc[(size_t)N_NODES * HID];
// W2 pre-paired: f2 idx ((cc*2+s)*4+tg)*512 + c  holds (W2[k][c], W2[k+4][c]), k=cc*16+s*8+tg
__device__ float g_W2p[(size_t)HID * HID];
// W3 pre-paired: f2 idx ((cc*4+s)*4+tg)*256 + c  holds (W3[k][c], W3[k+4][c]), k=cc*32+s*8+tg
__device__ float g_W3p[(size_t)HID * OUTD];

__device__ __forceinline__ float f2tf(float x) {
    uint32_t u; asm("cvt.rna.tf32.f32 %0, %1;" : "=r"(u) : "f"(x));
    return __uint_as_float(u);
}
__device__ __forceinline__ uint32_t smem_u32(const void* p) {
    uint32_t a;
    asm("{ .reg .u64 t; cvta.to.shared.u64 t, %1; cvt.u32.u64 %0, t; }" : "=r"(a) : "l"(p));
    return a;
}
__device__ __forceinline__ void mma8(float* d, const uint32_t* a,
                                     uint32_t b0, uint32_t b1) {
    asm volatile(
        "mma.sync.aligned.m16n8k8.row.col.f32.tf32.tf32.f32 "
        "{%0,%1,%2,%3},{%4,%5,%6,%7},{%8,%9},{%0,%1,%2,%3};"
        : "+f"(d[0]), "+f"(d[1]), "+f"(d[2]), "+f"(d[3])
        : "r"(a[0]), "r"(a[1]), "r"(a[2]), "r"(a[3]), "r"(b0), "r"(b1));
}
#define CP16(sa, gp) asm volatile("cp.async.cg.shared.global [%0], [%1], 16;" :: "r"(sa), "l"(gp) : "memory")
#define CP_COMMIT() asm volatile("cp.async.commit_group;" ::: "memory")
#define CP_WAIT0()  asm volatile("cp.async.wait_group 0;" ::: "memory")

// ---------------------------------------------------------------------------
// Kernel 1: per-node layer-1 precompute.
// ---------------------------------------------------------------------------
__global__ __launch_bounds__(512) void node_pre_kernel(
    const float* __restrict__ nf, const float* __restrict__ nh,
    const float* __restrict__ W1, const float* __restrict__ b1) {
    __shared__ float fs[64 * 161];
    const int nb = blockIdx.x * 64, tid = threadIdx.x;
    for (int idx = tid; idx < 64 * 160; idx += 512) {
        int m = idx / 160, k = idx % 160, n = nb + m;
        float v = 0.f;
        if (n < N_NODES)
            v = (k < F_DIM) ? nf[(size_t)n * F_DIM + k] : nh[(size_t)n * H_DIM + (k - F_DIM)];
        fs[m * 161 + k] = v;
    }
    __syncthreads();
    const int j = tid;
    float acc[64];
    const float bj = b1[j];
#pragma unroll
    for (int m = 0; m < 64; m++) acc[m] = bj;
    for (int k = 0; k < F_DIM; k++) {
        float w = __ldg(W1 + (size_t)k * HID + j);
#pragma unroll
        for (int m = 0; m < 64; m++) acc[m] += fs[m * 161 + k] * w;
    }
    for (int h = 0; h < H_DIM; h++) {
        float w = __ldg(W1 + (size_t)(32 + h) * HID + j) + __ldg(W1 + (size_t)(192 + h) * HID + j);
#pragma unroll
        for (int m = 0; m < 64; m++) acc[m] += fs[m * 161 + 32 + h] * w;
    }
    for (int m = 0; m < 64; m++) { int n = nb + m; if (n < N_NODES) g_Pdst[(size_t)n * HID + j] = acc[m]; }
#pragma unroll
    for (int m = 0; m < 64; m++) acc[m] = 0.f;
    for (int k = 0; k < F_DIM; k++) {
        float w = __ldg(W1 + (size_t)(160 + k) * HID + j);
#pragma unroll
        for (int m = 0; m < 64; m++) acc[m] += fs[m * 161 + k] * w;
    }
    for (int m = 0; m < 64; m++) { int n = nb + m; if (n < N_NODES) g_Psrc[(size_t)n * HID + j] = acc[m]; }
}

// ---------------------------------------------------------------------------
// Kernel 2: tf32-round + pair-interleave W2/W3 for float2 B-fragment loads.
// ---------------------------------------------------------------------------
__global__ void weight_prep_kernel(const float* __restrict__ W2, const float* __restrict__ W3) {
    int i = blockIdx.x * blockDim.x + threadIdx.x;
    if (i < 512 * 512) {
        int h = i & 1, q = i >> 1;
        int c = q & 511; q >>= 9;
        int tg = q & 3;  q >>= 2;
        int s = q & 1, cc = q >> 1;
        int k = cc * 16 + s * 8 + tg + 4 * h;
        g_W2p[i] = f2tf(W2[(size_t)k * HID + c]);
    } else if (i < 512 * 512 + 512 * 256) {
        int j = i - 512 * 512;
        int h = j & 1, q = j >> 1;
        int c = q & 255; q >>= 8;
        int tg = q & 3;  q >>= 2;
        int s = q & 3, cc = q >> 2;
        int k = cc * 32 + s * 8 + tg + 4 * h;
        g_W3p[j] = f2tf(W3[(size_t)k * OUTD + c]);
    }
}

// ---------------------------------------------------------------------------
// Kernel 3: fused layers 2+3. 64 edges/block, 512 threads = 16 warps (2m x 8n).
// hs pair-interleaved (A float2 loads); weights pre-paired (B float2 loads).
// One __syncthreads per chunk; L2 chunks = 16 k-rows, L3 chunks = 32 k-rows.
// ---------------------------------------------------------------------------
#define HS_STR 516
#define HS_F   (64 * HS_STR)             // 33024
#define BUF_F  8384                      // max(8*518, 16*262) f2 * 2 = floats
#define W2ROW  518                       // f2 stride per (s*4+tg) row, layer 2
#define W3ROW  262                       // f2 stride per (s*4+tg) row, layer 3
#define B2S_F  (HS_F + 2 * BUF_F)        // 49792
#define B3S_F  (B2S_F + 512)
#define W1S_F  (B3S_F + 256)
#define SMEM_BYTES ((W1S_F + 512) * 4)   // 204288

__global__ __launch_bounds__(512, 1) void edge_mlp_kernel(
    const int* __restrict__ src_idx, const int* __restrict__ dst_idx,
    const float* __restrict__ distance, const float* __restrict__ W1,
    const float* __restrict__ b2, const float* __restrict__ b3,
    float* __restrict__ out) {
    extern __shared__ float sm[];
    float* hs = sm;
    float* b2s = sm + B2S_F;
    float* b3s = sm + B3S_F;
    float* w1s = sm + W1S_F;
    const uint32_t wtu = smem_u32(sm + HS_F);

    const int tid = threadIdx.x, lane = tid & 31, warp = tid >> 5;
    const int wm = warp >> 3;   // 0..1
    const int wn = warp & 7;    // 0..7
    const int g = lane >> 2, tg = lane & 3;
    const int ebase = blockIdx.x * 64;

    b2s[tid & 511] = b2[tid & 511];
    if (tid < 512) w1s[tid] = W1[(size_t)320 * HID + tid];
    if (tid < 256) b3s[tid] = b3[tid];

    // prefetch W2 chunk 0 into buffer 0 (paired layout, 4 CP16/thread)
    {
#pragma unroll
        for (int i = 0; i < 4; i++) {
            int idx = tid + i * 512;
            int st = idx >> 8, c0 = (idx & 255) * 2;
            CP16(wtu + (st * W2ROW + c0) * 8, g_W2p + st * 1024 + c0 * 2);
        }
        CP_COMMIT();
    }
    __syncthreads();  // publish w1s/b2s/b3s

    // ---- stage h1 pair-interleaved: hs[m][kb*8+{0..7}] = h0,h4,h1,h5,h2,h6,h3,h7
    {
        const int m = tid >> 3, q = tid & 7;
        const int e = ebase + m;
        const int d = dst_idx[e], s_ = src_idx[e];
        const float dist = distance[e];
        const float4* pd = (const float4*)(g_Pdst + (size_t)d * HID);
        const float4* ps = (const float4*)(g_Psrc + (size_t)s_ * HID);
        float* hrow = hs + m * HS_STR;
#pragma unroll
        for (int t = 0; t < 8; t++) {
            int kb = t * 8 + q;
            float4 alo = __ldg(pd + 2 * kb), ahi = __ldg(pd + 2 * kb + 1);
            float4 blo = __ldg(ps + 2 * kb), bhi = __ldg(ps + 2 * kb + 1);
            float4 wlo = *(const float4*)(w1s + kb * 8);
            float4 whi = *(const float4*)(w1s + kb * 8 + 4);
            float h0 = f2tf(fmaxf(fmaf(dist, wlo.x, alo.x + blo.x), 0.f));
            float h1 = f2tf(fmaxf(fmaf(dist, wlo.y, alo.y + blo.y), 0.f));
            float h2 = f2tf(fmaxf(fmaf(dist, wlo.z, alo.z + blo.z), 0.f));
            float h3 = f2tf(fmaxf(fmaf(dist, wlo.w, alo.w + blo.w), 0.f));
            float h4 = f2tf(fmaxf(fmaf(dist, whi.x, ahi.x + bhi.x), 0.f));
            float h5 = f2tf(fmaxf(fmaf(dist, whi.y, ahi.y + bhi.y), 0.f));
            float h6 = f2tf(fmaxf(fmaf(dist, whi.z, ahi.z + bhi.z), 0.f));
            float h7 = f2tf(fmaxf(fmaf(dist, whi.w, ahi.w + bhi.w), 0.f));
            float4 o0 = {h0, h4, h1, h5};
            float4 o1 = {h2, h6, h3, h7};
            *(float4*)(hrow + kb * 8) = o0;
            *(float4*)(hrow + kb * 8 + 4) = o1;
        }
    }

    // ======================= Layer 2: 32 chunks of 16 k-rows =================
    float acc[2][8][4];
#pragma unroll
    for (int mt = 0; mt < 2; mt++)
#pragma unroll
        for (int nt = 0; nt < 8; nt++)
#pragma unroll
            for (int i = 0; i < 4; i++) acc[mt][nt][i] = 0.f;

    const int rA = wm * 32 + g;
    for (int cc = 0; cc < 32; cc++) {
        CP_WAIT0();
        __syncthreads();
        if (cc < 31) {
            const float* src = g_W2p + (size_t)(cc + 1) * 8192;
            const uint32_t dstu = wtu + ((cc + 1) & 1) * (BUF_F * 4);
#pragma unroll
            for (int i = 0; i < 4; i++) {
                int idx = tid + i * 512;
                int st = idx >> 8, c0 = (idx & 255) * 2;
                CP16(dstu + (st * W2ROW + c0) * 8, src + st * 1024 + c0 * 2);
            }
            CP_COMMIT();
        }
        const float2* wb = (const float2*)(sm + HS_F + (cc & 1) * BUF_F);
#pragma unroll
        for (int s = 0; s < 2; s++) {
            const int kb = cc * 2 + s;
            float2 al0 = *(const float2*)(hs + rA * HS_STR + kb * 8 + 2 * tg);
            float2 ah0 = *(const float2*)(hs + (rA + 8) * HS_STR + kb * 8 + 2 * tg);
            float2 al1 = *(const float2*)(hs + (rA + 16) * HS_STR + kb * 8 + 2 * tg);
            float2 ah1 = *(const float2*)(hs + (rA + 24) * HS_STR + kb * 8 + 2 * tg);
            uint32_t a0[4] = {__float_as_uint(al0.x), __float_as_uint(ah0.x),
                              __float_as_uint(al0.y), __float_as_uint(ah0.y)};
            uint32_t a1[4] = {__float_as_uint(al1.x), __float_as_uint(ah1.x),
                              __float_as_uint(al1.y), __float_as_uint(ah1.y)};
            const float2* wrow = wb + (s * 4 + tg) * W2ROW + wn * 64 + g;
#pragma unroll
            for (int nt = 0; nt < 8; nt++) {
                float2 b = wrow[nt * 8];
                uint32_t b0 = __float_as_uint(b.x), b1 = __float_as_uint(b.y);
                mma8(acc[0][nt], a0, b0, b1);
                mma8(acc[1][nt], a1, b0, b1);
            }
        }
    }

    // prefetch W3 chunk 0 into buffer 0 (safe: all warps past chunk30 reads)
    {
#pragma unroll
        for (int i = 0; i < 4; i++) {
            int idx = tid + i * 512;
            int st = idx >> 7, c0 = (idx & 127) * 2;
            CP16(wtu + (st * W3ROW + c0) * 8, g_W3p + st * 512 + c0 * 2);
        }
        CP_COMMIT();
    }
    __syncthreads();  // all warps done reading hs (layer2 A) before overwrite

    // ---- epilogue 2: h2 pair-interleaved back into hs ----
#pragma unroll
    for (int mt = 0; mt < 2; mt++)
#pragma unroll
        for (int nt = 0; nt < 8; nt++) {
            int r = wm * 32 + mt * 16 + g;
            int cbl = wn * 8 + nt;
            int c = cbl * 8 + tg * 2;
            int p0 = (tg < 2) ? 4 * tg : 4 * tg - 7;
            int p1 = (tg < 2) ? 4 * tg + 2 : 4 * tg - 5;
            float ba = b2s[c], bb = b2s[c + 1];
            hs[r * HS_STR + cbl * 8 + p0]       = f2tf(fmaxf(acc[mt][nt][0] + ba, 0.f));
            hs[r * HS_STR + cbl * 8 + p1]       = f2tf(fmaxf(acc[mt][nt][1] + bb, 0.f));
            hs[(r + 8) * HS_STR + cbl * 8 + p0] = f2tf(fmaxf(acc[mt][nt][2] + ba, 0.f));
            hs[(r + 8) * HS_STR + cbl * 8 + p1] = f2tf(fmaxf(acc[mt][nt][3] + bb, 0.f));
        }

    // ======================= Layer 3: 16 chunks of 32 k-rows =================
    float acc3[2][4][4];
#pragma unroll
    for (int mt = 0; mt < 2; mt++)
#pragma unroll
        for (int nt = 0; nt < 4; nt++)
#pragma unroll
            for (int i = 0; i < 4; i++) acc3[mt][nt][i] = 0.f;

    for (int c3 = 0; c3 < 16; c3++) {
        CP_WAIT0();
        __syncthreads();  // c3=0 also publishes epilogue-2 hs writes
        if (c3 < 15) {
            const float* src = g_W3p + (size_t)(c3 + 1) * 8192;
            const uint32_t dstu = wtu + ((c3 + 1) & 1) * (BUF_F * 4);
#pragma unroll
            for (int i = 0; i < 4; i++) {
                int idx = tid + i * 512;
                int st = idx >> 7, c0 = (idx & 127) * 2;
                CP16(dstu + (st * W3ROW + c0) * 8, src + st * 512 + c0 * 2);
            }
            CP_COMMIT();
        }
        const float2* wb = (const float2*)(sm + HS_F + (c3 & 1) * BUF_F);
#pragma unroll
        for (int s = 0; s < 4; s++) {
            const int kb = c3 * 4 + s;
            float2 al0 = *(const float2*)(hs + rA * HS_STR + kb * 8 + 2 * tg);
            float2 ah0 = *(const float2*)(hs + (rA + 8) * HS_STR + kb * 8 + 2 * tg);
            float2 al1 = *(const float2*)(hs + (rA + 16) * HS_STR + kb * 8 + 2 * tg);
            float2 ah1 = *(const float2*)(hs + (rA + 24) * HS_STR + kb * 8 + 2 * tg);
            uint32_t a0[4] = {__float_as_uint(al0.x), __float_as_uint(ah0.x),
                              __float_as_uint(al0.y), __float_as_uint(ah0.y)};
            uint32_t a1[4] = {__float_as_uint(al1.x), __float_as_uint(ah1.x),
                              __float_as_uint(al1.y), __float_as_uint(ah1.y)};
            const float2* wrow = wb + (s * 4 + tg) * W3ROW + wn * 32 + g;
#pragma unroll
            for (int nt = 0; nt < 4; nt++) {
                float2 b = wrow[nt * 8];
                uint32_t b0 = __float_as_uint(b.x), b1 = __float_as_uint(b.y);
                mma8(acc3[0][nt], a0, b0, b1);
                mma8(acc3[1][nt], a1, b0, b1);
            }
        }
    }

    // ---- epilogue 3: out = acc3 + b3 ----
#pragma unroll
    for (int mt = 0; mt < 2; mt++)
#pragma unroll
        for (int nt = 0; nt < 4; nt++) {
            int r = wm * 32 + mt * 16 + g;
            int c = wn * 32 + nt * 8 + tg * 2;
            size_t row0 = (size_t)(ebase + r) * OUTD;
            size_t row8 = (size_t)(ebase + r + 8) * OUTD;
            float ba = b3s[c], bb = b3s[c + 1];
            out[row0 + c]     = acc3[mt][nt][0] + ba;
            out[row0 + c + 1] = acc3[mt][nt][1] + bb;
            out[row8 + c]     = acc3[mt][nt][2] + ba;
            out[row8 + c + 1] = acc3[mt][nt][3] + bb;
        }
}

// -----------------------------------------------------------------------------
extern "C" void kernel_launch(void* const* d_in, const int* in_sizes, int n_in,
                              void* d_out, int out_size) {
    const float* nf   = (const float*)d_in[0];
    const float* nh   = (const float*)d_in[1];
    const int*   src  = (const int*)d_in[2];
    const int*   dst  = (const int*)d_in[3];
    const float* dist = (const float*)d_in[4];
    const float* W1   = (const float*)d_in[5];
    const float* b1   = (const float*)d_in[6];
    const float* W2   = (const float*)d_in[7];
    const float* b2   = (const float*)d_in[8];
    const float* W3   = (const float*)d_in[9];
    const float* b3   = (const float*)d_in[10];
    float* out = (float*)d_out;

    static bool attr_set = false;
    if (!attr_set) {
        cudaFuncSetAttribute(edge_mlp_kernel,
                             cudaFuncAttributeMaxDynamicSharedMemorySize, SMEM_BYTES);
        attr_set = true;
    }
    node_pre_kernel<<<(N_NODES + 63) / 64, 512>>>(nf, nh, W1, b1);
    weight_prep_kernel<<<(HID * HID + HID * OUTD + 255) / 256, 256>>>(W2, W3);
    edge_mlp_kernel<<<N_EDGES / 64, 512, SMEM_BYTES>>>(src, dst, dist, W1, b2, b3, out);
}

// round 9
// speedup vs baseline: 2.1340x; 2.1340x over previous
#include <cuda_runtime.h>
#include <cuda_fp16.h>
#include <cstdint>

#define N_NODES 50000
#define N_EDGES 1600000
#define F_DIM 32
#define H_DIM 128
#define HID 512
#define OUTD 256

// Scratch (__device__ globals = allocation-guard-legal scratch)
__device__ float g_Pdst[(size_t)N_NODES * HID];
__device__ float g_Psrc[(size_t)N_NODES * HID];
// fp16 weights pre-packed as B-fragment half2 words:
// word row R (0..255): cc=R>>4, s=(R>>3)&1, j=R&7 -> k0 = cc*32+s*16+2j
// g_W2h[R*512 + c] = half2(W2[k0][c], W2[k0+1][c]);  g_W3h[R*256 + c] likewise.
__device__ __align__(16) uint32_t g_W2h[(size_t)256 * 512];
__device__ __align__(16) uint32_t g_W3h[(size_t)256 * 256];

__device__ __forceinline__ uint32_t smem_u32(const void* p) {
    uint32_t a;
    asm("{ .reg .u64 t; cvta.to.shared.u64 t, %1; cvt.u32.u64 %0, t; }" : "=r"(a) : "l"(p));
    return a;
}
__device__ __forceinline__ void mma16(float* d, const uint32_t* a,
                                      uint32_t b0, uint32_t b1) {
    asm volatile(
        "mma.sync.aligned.m16n8k16.row.col.f32.f16.f16.f32 "
        "{%0,%1,%2,%3},{%4,%5,%6,%7},{%8,%9},{%0,%1,%2,%3};"
        : "+f"(d[0]), "+f"(d[1]), "+f"(d[2]), "+f"(d[3])
        : "r"(a[0]), "r"(a[1]), "r"(a[2]), "r"(a[3]), "r"(b0), "r"(b1));
}
__device__ __forceinline__ uint32_t pack2(float x, float y) {
    __half2 h = __floats2half2_rn(x, y);
    return *(uint32_t*)&h;
}
#define CP16(sa, gp) asm volatile("cp.async.cg.shared.global [%0], [%1], 16;" :: "r"(sa), "l"(gp) : "memory")
#define CP_COMMIT() asm volatile("cp.async.commit_group;" ::: "memory")
#define CP_WAIT1()  asm volatile("cp.async.wait_group 1;" ::: "memory")

// ---------------------------------------------------------------------------
// Kernel 1: per-node layer-1 precompute (unchanged, proven).
// ---------------------------------------------------------------------------
__global__ __launch_bounds__(512) void node_pre_kernel(
    const float* __restrict__ nf, const float* __restrict__ nh,
    const float* __restrict__ W1, const float* __restrict__ b1) {
    __shared__ float fs[64 * 161];
    const int nb = blockIdx.x * 64, tid = threadIdx.x;
    for (int idx = tid; idx < 64 * 160; idx += 512) {
        int m = idx / 160, k = idx % 160, n = nb + m;
        float v = 0.f;
        if (n < N_NODES)
            v = (k < F_DIM) ? nf[(size_t)n * F_DIM + k] : nh[(size_t)n * H_DIM + (k - F_DIM)];
        fs[m * 161 + k] = v;
    }
    __syncthreads();
    const int j = tid;
    float acc[64];
    const float bj = b1[j];
#pragma unroll
    for (int m = 0; m < 64; m++) acc[m] = bj;
    for (int k = 0; k < F_DIM; k++) {
        float w = __ldg(W1 + (size_t)k * HID + j);
#pragma unroll
        for (int m = 0; m < 64; m++) acc[m] += fs[m * 161 + k] * w;
    }
    for (int h = 0; h < H_DIM; h++) {
        float w = __ldg(W1 + (size_t)(32 + h) * HID + j) + __ldg(W1 + (size_t)(192 + h) * HID + j);
#pragma unroll
        for (int m = 0; m < 64; m++) acc[m] += fs[m * 161 + 32 + h] * w;
    }
    for (int m = 0; m < 64; m++) { int n = nb + m; if (n < N_NODES) g_Pdst[(size_t)n * HID + j] = acc[m]; }
#pragma unroll
    for (int m = 0; m < 64; m++) acc[m] = 0.f;
    for (int k = 0; k < F_DIM; k++) {
        float w = __ldg(W1 + (size_t)(160 + k) * HID + j);
#pragma unroll
        for (int m = 0; m < 64; m++) acc[m] += fs[m * 161 + k] * w;
    }
    for (int m = 0; m < 64; m++) { int n = nb + m; if (n < N_NODES) g_Psrc[(size_t)n * HID + j] = acc[m]; }
}

// ---------------------------------------------------------------------------
// Kernel 2: fp16-convert + fragment-pack W2/W3.
// ---------------------------------------------------------------------------
__global__ void weight_prep_kernel(const float* __restrict__ W2, const float* __restrict__ W3) {
    int i = blockIdx.x * blockDim.x + threadIdx.x;
    if (i < 256 * 512) {
        int c = i & 511, R = i >> 9;
        int cc = R >> 4, s = (R >> 3) & 1, j = R & 7;
        int k0 = cc * 32 + s * 16 + 2 * j;
        g_W2h[i] = pack2(W2[(size_t)k0 * HID + c], W2[(size_t)(k0 + 1) * HID + c]);
    } else if (i < 256 * 512 + 256 * 256) {
        int q = i - 256 * 512;
        int c = q & 255, R = q >> 8;
        int cc = R >> 4, s = (R >> 3) & 1, j = R & 7;
        int k0 = cc * 32 + s * 16 + 2 * j;
        g_W3h[q] = pack2(W3[(size_t)k0 * OUTD + c], W3[(size_t)(k0 + 1) * OUTD + c]);
    }
}

// ---------------------------------------------------------------------------
// Kernel 3: fused layers 2+3, fp16 mma.sync.m16n8k16, fp32 accum.
// 64 edges/block, 512 threads = 16 warps (2m x 8n).
// hs: half[64][520], word stride 260 (== 4 mod 32 -> A banks 4g+tg, clean).
// Weights: 3-buffer cp.async ring (k32 chunks), word strides 520/264
// (bank 8tg+g+8nt, conflict-free). One sync per chunk.
// ---------------------------------------------------------------------------
#define HS_STRW 260                // words per hs row (256 data + 4 pad)
#define HS_W   (64 * HS_STRW)      // 16640 words
#define BUF_W  8320                // 16 x 520 words (W3 chunk 16x264 fits)
#define B2S_W  (HS_W + 3 * BUF_W)  // 41600
#define B3S_W  (B2S_W + 512)
#define W1S_W  (B3S_W + 256)
#define SMEM_BYTES ((W1S_W + 512) * 4)  // 171520

__device__ __forceinline__ void prefetch_chunk(int t, uint32_t wtu, int tid) {
    if (t < 16) {
        const uint32_t* srcw = g_W2h + (size_t)t * 8192;
        uint32_t dstu = wtu + (uint32_t)(t % 3) * (BUF_W * 4);
#pragma unroll
        for (int i = 0; i < 4; i++) {
            int idx = tid + i * 512;
            int wr = idx >> 7, c0 = (idx & 127) * 4;
            CP16(dstu + (wr * 520 + c0) * 4, srcw + wr * 512 + c0);
        }
    } else if (t < 32) {
        const uint32_t* srcw = g_W3h + (size_t)(t - 16) * 4096;
        uint32_t dstu = wtu + (uint32_t)(t % 3) * (BUF_W * 4);
#pragma unroll
        for (int i = 0; i < 2; i++) {
            int idx = tid + i * 512;
            int wr = idx >> 6, c0 = (idx & 63) * 4;
            CP16(dstu + (wr * 264 + c0) * 4, srcw + wr * 256 + c0);
        }
    }
    CP_COMMIT();  // empty group for t>=32 keeps wait_group arithmetic uniform
}

__global__ __launch_bounds__(512, 1) void edge_mlp_kernel(
    const int* __restrict__ src_idx, const int* __restrict__ dst_idx,
    const float* __restrict__ distance, const float* __restrict__ W1,
    const float* __restrict__ b2, const float* __restrict__ b3,
    float* __restrict__ out) {
    extern __shared__ float sm[];
    uint32_t* smw = (uint32_t*)sm;
    float* b2s = sm + B2S_W;
    float* b3s = sm + B3S_W;
    float* w1s = sm + W1S_W;
    const uint32_t wtu = smem_u32(smw + HS_W);

    const int tid = threadIdx.x, lane = tid & 31, warp = tid >> 5;
    const int wm = warp >> 3;   // 0..1
    const int wn = warp & 7;    // 0..7
    const int g = lane >> 2, tg = lane & 3;
    const int ebase = blockIdx.x * 64;
    const int rA = wm * 32 + g;

    b2s[tid & 511] = b2[tid & 511];
    if (tid < 512) w1s[tid] = W1[(size_t)320 * HID + tid];
    if (tid < 256) b3s[tid] = b3[tid];

    prefetch_chunk(0, wtu, tid);
    prefetch_chunk(1, wtu, tid);
    __syncthreads();  // publish w1s before staging reads it

    // ---- stage h1 = half(relu(Pdst[dst] + Psrc[src] + dist*W1[320])) ----
    // Each thread: edge m = tid>>3, 8 uint4 (u = t*8+q), u covers halves [8u, 8u+8).
    {
        const int m = tid >> 3, q = tid & 7;
        const int e = ebase + m;
        const int dI = dst_idx[e], sI = src_idx[e];
        const float dist = distance[e];
        const float4* pd = (const float4*)(g_Pdst + (size_t)dI * HID);
        const float4* ps = (const float4*)(g_Psrc + (size_t)sI * HID);
        uint32_t* hrow = smw + m * HS_STRW;
#pragma unroll
        for (int t = 0; t < 8; t++) {
            int u = t * 8 + q;  // 0..63
            float4 aL = __ldg(pd + 2 * u), aH = __ldg(pd + 2 * u + 1);
            float4 bL = __ldg(ps + 2 * u), bH = __ldg(ps + 2 * u + 1);
            float4 wL = *(const float4*)(w1s + u * 8);
            float4 wH = *(const float4*)(w1s + u * 8 + 4);
            uint4 o;
            o.x = pack2(fmaxf(fmaf(dist, wL.x, aL.x + bL.x), 0.f),
                        fmaxf(fmaf(dist, wL.y, aL.y + bL.y), 0.f));
            o.y = pack2(fmaxf(fmaf(dist, wL.z, aL.z + bL.z), 0.f),
                        fmaxf(fmaf(dist, wL.w, aL.w + bL.w), 0.f));
            o.z = pack2(fmaxf(fmaf(dist, wH.x, aH.x + bH.x), 0.f),
                        fmaxf(fmaf(dist, wH.y, aH.y + bH.y), 0.f));
            o.w = pack2(fmaxf(fmaf(dist, wH.z, aH.z + bH.z), 0.f),
                        fmaxf(fmaf(dist, wH.w, aH.w + bH.w), 0.f));
            *(uint4*)(hrow + u * 4) = o;
        }
    }

    // =================== Layer 2: 16 chunks of k=32 =========================
    float acc[2][8][4];
#pragma unroll
    for (int mt = 0; mt < 2; mt++)
#pragma unroll
        for (int nt = 0; nt < 8; nt++)
#pragma unroll
            for (int i = 0; i < 4; i++) acc[mt][nt][i] = 0.f;

    for (int cc = 0; cc < 16; cc++) {
        CP_WAIT1();          // chunk cc resident (cc+1 may be in flight)
        __syncthreads();     // all warps done with buffer (cc-1)%3
        prefetch_chunk(cc + 2, wtu, tid);
        const uint32_t* wb = smw + HS_W + (cc % 3) * BUF_W;
#pragma unroll
        for (int s = 0; s < 2; s++) {
            const int kw = cc * 16 + s * 8;  // word offset in hs (k = 2*kw)
            uint32_t a0[4], a1[4];
            a0[0] = smw[rA * HS_STRW + kw + tg];
            a0[1] = smw[(rA + 8) * HS_STRW + kw + tg];
            a0[2] = smw[rA * HS_STRW + kw + tg + 4];
            a0[3] = smw[(rA + 8) * HS_STRW + kw + tg + 4];
            a1[0] = smw[(rA + 16) * HS_STRW + kw + tg];
            a1[1] = smw[(rA + 24) * HS_STRW + kw + tg];
            a1[2] = smw[(rA + 16) * HS_STRW + kw + tg + 4];
            a1[3] = smw[(rA + 24) * HS_STRW + kw + tg + 4];
            const uint32_t* wrow = wb + (s * 8 + tg) * 520 + wn * 64 + g;
#pragma unroll
            for (int nt = 0; nt < 8; nt++) {
                uint32_t b0 = wrow[nt * 8];
                uint32_t b1 = wrow[4 * 520 + nt * 8];
                mma16(acc[0][nt], a0, b0, b1);
                mma16(acc[1][nt], a1, b0, b1);
            }
        }
    }
    __syncthreads();  // all hs (layer-2 A) reads done before overwrite

    // ---- epilogue 2: h2 = half(relu(acc + b2)) back into hs ----
#pragma unroll
    for (int mt = 0; mt < 2; mt++)
#pragma unroll
        for (int nt = 0; nt < 8; nt++) {
            int r = wm * 32 + mt * 16 + g;
            int cw = wn * 32 + nt * 4 + tg;  // word col; c = 2*cw
            int c = 2 * cw;
            float ba = b2s[c], bb = b2s[c + 1];
            smw[r * HS_STRW + cw] = pack2(fmaxf(acc[mt][nt][0] + ba, 0.f),
                                          fmaxf(acc[mt][nt][1] + bb, 0.f));
            smw[(r + 8) * HS_STRW + cw] = pack2(fmaxf(acc[mt][nt][2] + ba, 0.f),
                                                fmaxf(acc[mt][nt][3] + bb, 0.f));
        }

    // =================== Layer 3: 16 chunks of k=32 =========================
    float acc3[2][4][4];
#pragma unroll
    for (int mt = 0; mt < 2; mt++)
#pragma unroll
        for (int nt = 0; nt < 4; nt++)
#pragma unroll
            for (int i = 0; i < 4; i++) acc3[mt][nt][i] = 0.f;

    for (int g3 = 0; g3 < 16; g3++) {
        CP_WAIT1();
        __syncthreads();  // g3==0 also publishes epilogue-2 hs writes
        prefetch_chunk(18 + g3, wtu, tid);
        const uint32_t* wb = smw + HS_W + ((16 + g3) % 3) * BUF_W;
#pragma unroll
        for (int s = 0; s < 2; s++) {
            const int kw = g3 * 16 + s * 8;
            uint32_t a0[4], a1[4];
            a0[0] = smw[rA * HS_STRW + kw + tg];
            a0[1] = smw[(rA + 8) * HS_STRW + kw + tg];
            a0[2] = smw[rA * HS_STRW + kw + tg + 4];
            a0[3] = smw[(rA + 8) * HS_STRW + kw + tg + 4];
            a1[0] = smw[(rA + 16) * HS_STRW + kw + tg];
            a1[1] = smw[(rA + 24) * HS_STRW + kw + tg];
            a1[2] = smw[(rA + 16) * HS_STRW + kw + tg + 4];
            a1[3] = smw[(rA + 24) * HS_STRW + kw + tg + 4];
            const uint32_t* wrow = wb + (s * 8 + tg) * 264 + wn * 32 + g;
#pragma unroll
            for (int nt = 0; nt < 4; nt++) {
                uint32_t b0 = wrow[nt * 8];
                uint32_t b1 = wrow[4 * 264 + nt * 8];
                mma16(acc3[0][nt], a0, b0, b1);
                mma16(acc3[1][nt], a1, b0, b1);
            }
        }
    }

    // ---- epilogue 3: out = acc3 + b3 (fp32) ----
#pragma unroll
    for (int mt = 0; mt < 2; mt++)
#pragma unroll
        for (int nt = 0; nt < 4; nt++) {
            int r = wm * 32 + mt * 16 + g;
            int c = wn * 32 + nt * 8 + tg * 2;
            size_t row0 = (size_t)(ebase + r) * OUTD;
            size_t row8 = (size_t)(ebase + r + 8) * OUTD;
            float ba = b3s[c], bb = b3s[c + 1];
            out[row0 + c]     = acc3[mt][nt][0] + ba;
            out[row0 + c + 1] = acc3[mt][nt][1] + bb;
            out[row8 + c]     = acc3[mt][nt][2] + ba;
            out[row8 + c + 1] = acc3[mt][nt][3] + bb;
        }
}

// -----------------------------------------------------------------------------
extern "C" void kernel_launch(void* const* d_in, const int* in_sizes, int n_in,
                              void* d_out, int out_size) {
    const float* nf   = (const float*)d_in[0];
    const float* nh   = (const float*)d_in[1];
    const int*   src  = (const int*)d_in[2];
    const int*   dst  = (const int*)d_in[3];
    const float* dist = (const float*)d_in[4];
    const float* W1   = (const float*)d_in[5];
    const float* b1   = (const float*)d_in[6];
    const float* W2   = (const float*)d_in[7];
    const float* b2   = (const float*)d_in[8];
    const float* W3   = (const float*)d_in[9];
    const float* b3   = (const float*)d_in[10];
    float* out = (float*)d_out;

    static bool attr_set = false;
    if (!attr_set) {
        cudaFuncSetAttribute(edge_mlp_kernel,
                             cudaFuncAttributeMaxDynamicSharedMemorySize, SMEM_BYTES);
        attr_set = true;
    }
    node_pre_kernel<<<(N_NODES + 63) / 64, 512>>>(nf, nh, W1, b1);
    weight_prep_kernel<<<(256 * 512 + 256 * 256 + 255) / 256, 256>>>(W2, W3);
    edge_mlp_kernel<<<N_EDGES / 64, 512, SMEM_BYTES>>>(src, dst, dist, W1, b2, b3, out);
}

// round 10
// speedup vs baseline: 2.5045x; 1.1736x over previous
#include <cuda_runtime.h>
#include <cuda_fp16.h>
#include <cstdint>

#define N_NODES 50000
#define N_EDGES 1600000
#define F_DIM 32
#define H_DIM 128
#define HID 512
#define OUTD 256

// Scratch (__device__ globals = allocation-guard-legal scratch)
__device__ __align__(16) __half g_PdstH[(size_t)N_NODES * HID];
__device__ __align__(16) __half g_PsrcH[(size_t)N_NODES * HID];
// fp16 weights pre-packed as B-fragment uint2: row R (0..127):
// cc=R>>3, s=(R>>2)&1, j=R&3 -> k0 = cc*32+s*16+2j
// g_W2q[R*512+c] = { half2(W2[k0][c],W2[k0+1][c]), half2(W2[k0+8][c],W2[k0+9][c]) }
__device__ __align__(16) uint2 g_W2q[(size_t)128 * 512];
__device__ __align__(16) uint2 g_W3q[(size_t)128 * 256];

__device__ __forceinline__ uint32_t smem_u32(const void* p) {
    uint32_t a;
    asm("{ .reg .u64 t; cvta.to.shared.u64 t, %1; cvt.u32.u64 %0, t; }" : "=r"(a) : "l"(p));
    return a;
}
__device__ __forceinline__ void mma16(float* d, const uint32_t* a,
                                      uint32_t b0, uint32_t b1) {
    asm volatile(
        "mma.sync.aligned.m16n8k16.row.col.f32.f16.f16.f32 "
        "{%0,%1,%2,%3},{%4,%5,%6,%7},{%8,%9},{%0,%1,%2,%3};"
        : "+f"(d[0]), "+f"(d[1]), "+f"(d[2]), "+f"(d[3])
        : "r"(a[0]), "r"(a[1]), "r"(a[2]), "r"(a[3]), "r"(b0), "r"(b1));
}
__device__ __forceinline__ uint32_t pack2(float x, float y) {
    __half2 h = __floats2half2_rn(x, y);
    return *(uint32_t*)&h;
}
// h1 elementwise op on a half2 word: max(a + b + d*w, 0)
__device__ __forceinline__ uint32_t h1op(uint32_t a, uint32_t b, uint32_t w,
                                         __half2 d2) {
    __half2 r = __hfma2(d2, *(__half2*)&w,
                        __hadd2(*(__half2*)&a, *(__half2*)&b));
    r = __hmax2(r, __floats2half2_rn(0.f, 0.f));
    return *(uint32_t*)&r;
}
#define CP16(sa, gp) asm volatile("cp.async.cg.shared.global [%0], [%1], 16;" :: "r"(sa), "l"(gp) : "memory")
#define CP_COMMIT() asm volatile("cp.async.commit_group;" ::: "memory")
#define CP_WAIT1()  asm volatile("cp.async.wait_group 1;" ::: "memory")

// ---------------------------------------------------------------------------
// Kernel 1: per-node layer-1 precompute. fs transposed [k][m] for float4
// broadcast loads (LDS instr / 4); outputs stored as fp16.
// ---------------------------------------------------------------------------
__global__ __launch_bounds__(512) void node_pre_kernel(
    const float* __restrict__ nf, const float* __restrict__ nh,
    const float* __restrict__ W1, const float* __restrict__ b1) {
    __shared__ float fs[160 * 68];  // fs[k][m], stride 68 (272B, 16B-aligned)
    const int nb = blockIdx.x * 64, tid = threadIdx.x;
    for (int idx = tid; idx < 64 * 160; idx += 512) {
        int k = idx >> 6, m = idx & 63, n = nb + m;
        float v = 0.f;
        if (n < N_NODES)
            v = (k < F_DIM) ? nf[(size_t)n * F_DIM + k] : nh[(size_t)n * H_DIM + (k - F_DIM)];
        fs[k * 68 + m] = v;
    }
    __syncthreads();
    const int j = tid;
    float acc[64];
    const float bj = b1[j];
#pragma unroll
    for (int m = 0; m < 64; m++) acc[m] = bj;

    for (int k = 0; k < F_DIM; k++) {
        float w = __ldg(W1 + (size_t)k * HID + j);
        const float4* f4 = (const float4*)(fs + k * 68);
#pragma unroll
        for (int mq = 0; mq < 16; mq++) {
            float4 f = f4[mq];
            acc[4 * mq + 0] += f.x * w; acc[4 * mq + 1] += f.y * w;
            acc[4 * mq + 2] += f.z * w; acc[4 * mq + 3] += f.w * w;
        }
    }
    for (int h = 0; h < H_DIM; h++) {
        float w = __ldg(W1 + (size_t)(32 + h) * HID + j) +
                  __ldg(W1 + (size_t)(192 + h) * HID + j);
        const float4* f4 = (const float4*)(fs + (32 + h) * 68);
#pragma unroll
        for (int mq = 0; mq < 16; mq++) {
            float4 f = f4[mq];
            acc[4 * mq + 0] += f.x * w; acc[4 * mq + 1] += f.y * w;
            acc[4 * mq + 2] += f.z * w; acc[4 * mq + 3] += f.w * w;
        }
    }
    for (int m = 0; m < 64; m++) {
        int n = nb + m;
        if (n < N_NODES) g_PdstH[(size_t)n * HID + j] = __float2half(acc[m]);
    }
#pragma unroll
    for (int m = 0; m < 64; m++) acc[m] = 0.f;
    for (int k = 0; k < F_DIM; k++) {
        float w = __ldg(W1 + (size_t)(160 + k) * HID + j);
        const float4* f4 = (const float4*)(fs + k * 68);
#pragma unroll
        for (int mq = 0; mq < 16; mq++) {
            float4 f = f4[mq];
            acc[4 * mq + 0] += f.x * w; acc[4 * mq + 1] += f.y * w;
            acc[4 * mq + 2] += f.z * w; acc[4 * mq + 3] += f.w * w;
        }
    }
    for (int m = 0; m < 64; m++) {
        int n = nb + m;
        if (n < N_NODES) g_PsrcH[(size_t)n * HID + j] = __float2half(acc[m]);
    }
}

// ---------------------------------------------------------------------------
// Kernel 2: fp16-convert + uint2 fragment-pack W2/W3.
// ---------------------------------------------------------------------------
__global__ void weight_prep_kernel(const float* __restrict__ W2, const float* __restrict__ W3) {
    int i = blockIdx.x * blockDim.x + threadIdx.x;
    if (i < 128 * 512) {
        int c = i & 511, R = i >> 9;
        int cc = R >> 3, r = R & 7, s = r >> 2, j = r & 3;
        int k0 = cc * 32 + s * 16 + 2 * j;
        g_W2q[i] = make_uint2(
            pack2(W2[(size_t)k0 * HID + c], W2[(size_t)(k0 + 1) * HID + c]),
            pack2(W2[(size_t)(k0 + 8) * HID + c], W2[(size_t)(k0 + 9) * HID + c]));
    } else if (i < 128 * 512 + 128 * 256) {
        int q = i - 128 * 512;
        int c = q & 255, R = q >> 8;
        int cc = R >> 3, r = R & 7, s = r >> 2, j = r & 3;
        int k0 = cc * 32 + s * 16 + 2 * j;
        g_W3q[q] = make_uint2(
            pack2(W3[(size_t)k0 * OUTD + c], W3[(size_t)(k0 + 1) * OUTD + c]),
            pack2(W3[(size_t)(k0 + 8) * OUTD + c], W3[(size_t)(k0 + 9) * OUTD + c]));
    }
}

// ---------------------------------------------------------------------------
// Kernel 3: fused layers 2+3, fp16 mma.sync.m16n8k16, fp32 accum.
// 64 edges/block, 512 threads = 16 warps (2m x 8n).
// hs: half[64], word stride 260 (==4 mod 32, A banks 4g+tg, clean).
// Weights: 3-buffer ring of uint2 B-fragments; u2 row strides 516/260
// (word strides 1032/520 == 8 mod 32 -> LDS.64 conflict-free).
// ---------------------------------------------------------------------------
#define HS_STRW 260                // words per hs row (256 data + 4 pad)
#define HS_W   (64 * HS_STRW)      // 16640 words
#define BUF_W  8320                // >= 8 rows * 1032 words (W2 chunk)
#define B2S_W  (HS_W + 3 * BUF_W)  // 41600
#define B3S_W  (B2S_W + 512)
#define W1H_W  (B3S_W + 256)
#define SMEM_BYTES ((W1H_W + 256) * 4)  // 170496

__device__ __forceinline__ void prefetch_chunk(int t, uint32_t wtu, int tid) {
    if (t < 16) {
        const uint2* srcq = g_W2q + (size_t)t * 4096;  // 8 rows x 512 u2
        uint32_t dstu = wtu + (uint32_t)(t % 3) * (BUF_W * 4);
#pragma unroll
        for (int i = 0; i < 4; i++) {
            int idx = tid + i * 512;
            int wr = idx >> 8, c0 = (idx & 255) * 2;
            CP16(dstu + (uint32_t)(wr * 516 + c0) * 8, srcq + wr * 512 + c0);
        }
    } else if (t < 32) {
        const uint2* srcq = g_W3q + (size_t)(t - 16) * 2048;  // 8 rows x 256 u2
        uint32_t dstu = wtu + (uint32_t)(t % 3) * (BUF_W * 4);
#pragma unroll
        for (int i = 0; i < 2; i++) {
            int idx = tid + i * 512;
            int wr = idx >> 7, c0 = (idx & 127) * 2;
            CP16(dstu + (uint32_t)(wr * 260 + c0) * 8, srcq + wr * 256 + c0);
        }
    }
    CP_COMMIT();  // empty group for t>=32 keeps wait_group arithmetic uniform
}

__global__ __launch_bounds__(512, 1) void edge_mlp_kernel(
    const int* __restrict__ src_idx, const int* __restrict__ dst_idx,
    const float* __restrict__ distance, const float* __restrict__ W1,
    const float* __restrict__ b2, const float* __restrict__ b3,
    float* __restrict__ out) {
    extern __shared__ float sm[];
    uint32_t* smw = (uint32_t*)sm;
    float* b2s = sm + B2S_W;
    float* b3s = sm + B3S_W;
    uint32_t* w1h = smw + W1H_W;
    const uint32_t wtu = smem_u32(smw + HS_W);

    const int tid = threadIdx.x, lane = tid & 31, warp = tid >> 5;
    const int wm = warp >> 3;   // 0..1
    const int wn = warp & 7;    // 0..7
    const int g = lane >> 2, tg = lane & 3;
    const int ebase = blockIdx.x * 64;
    const int rA = wm * 32 + g;

    b2s[tid & 511] = b2[tid & 511];
    if (tid < 256) {
        w1h[tid] = pack2(W1[(size_t)320 * HID + 2 * tid],
                         W1[(size_t)320 * HID + 2 * tid + 1]);
        b3s[tid] = b3[tid];
    }

    prefetch_chunk(0, wtu, tid);
    prefetch_chunk(1, wtu, tid);
    __syncthreads();  // publish w1h before staging reads it

    // ---- stage h1 = half(relu(PdstH[dst] + PsrcH[src] + dist*W1[320])) ----
    {
        const int m = tid >> 3, q = tid & 7;
        const int e = ebase + m;
        const int dI = dst_idx[e], sI = src_idx[e];
        const __half2 d2 = __float2half2_rn(distance[e]);
        const uint4* pd = (const uint4*)(g_PdstH + (size_t)dI * HID);
        const uint4* ps = (const uint4*)(g_PsrcH + (size_t)sI * HID);
        uint32_t* hrow = smw + m * HS_STRW;
#pragma unroll
        for (int t = 0; t < 8; t++) {
            int u = t * 8 + q;  // 0..63, covers halves [8u, 8u+8)
            uint4 A = __ldg(pd + u);
            uint4 B = __ldg(ps + u);
            uint4 W = *(const uint4*)(w1h + u * 4);
            uint4 o;
            o.x = h1op(A.x, B.x, W.x, d2);
            o.y = h1op(A.y, B.y, W.y, d2);
            o.z = h1op(A.z, B.z, W.z, d2);
            o.w = h1op(A.w, B.w, W.w, d2);
            *(uint4*)(hrow + u * 4) = o;
        }
    }

    // =================== Layer 2: 16 chunks of k=32 =========================
    float acc[2][8][4];
#pragma unroll
    for (int mt = 0; mt < 2; mt++)
#pragma unroll
        for (int nt = 0; nt < 8; nt++)
#pragma unroll
            for (int i = 0; i < 4; i++) acc[mt][nt][i] = 0.f;

    for (int cc = 0; cc < 16; cc++) {
        CP_WAIT1();          // chunk cc resident (cc+1 may be in flight)
        __syncthreads();     // all warps done with buffer (cc-1)%3
        prefetch_chunk(cc + 2, wtu, tid);
        const uint2* wbu = (const uint2*)(smw + HS_W + (cc % 3) * BUF_W);
#pragma unroll
        for (int s = 0; s < 2; s++) {
            const int kw = cc * 16 + s * 8;  // word offset in hs (k = 2*kw)
            uint32_t a0[4], a1[4];
            a0[0] = smw[rA * HS_STRW + kw + tg];
            a0[1] = smw[(rA + 8) * HS_STRW + kw + tg];
            a0[2] = smw[rA * HS_STRW + kw + tg + 4];
            a0[3] = smw[(rA + 8) * HS_STRW + kw + tg + 4];
            a1[0] = smw[(rA + 16) * HS_STRW + kw + tg];
            a1[1] = smw[(rA + 24) * HS_STRW + kw + tg];
            a1[2] = smw[(rA + 16) * HS_STRW + kw + tg + 4];
            a1[3] = smw[(rA + 24) * HS_STRW + kw + tg + 4];
            const uint2* wrow = wbu + (s * 4 + tg) * 516 + wn * 64 + g;
#pragma unroll
            for (int nt = 0; nt < 8; nt++) {
                uint2 b = wrow[nt * 8];
                mma16(acc[0][nt], a0, b.x, b.y);
                mma16(acc[1][nt], a1, b.x, b.y);
            }
        }
    }
    __syncthreads();  // all hs (layer-2 A) reads done before overwrite

    // ---- epilogue 2: h2 = half(relu(acc + b2)) back into hs ----
#pragma unroll
    for (int mt = 0; mt < 2; mt++)
#pragma unroll
        for (int nt = 0; nt < 8; nt++) {
            int r = wm * 32 + mt * 16 + g;
            int cw = wn * 32 + nt * 4 + tg;  // word col; c = 2*cw
            int c = 2 * cw;
            float ba = b2s[c], bb = b2s[c + 1];
            smw[r * HS_STRW + cw] = pack2(fmaxf(acc[mt][nt][0] + ba, 0.f),
                                          fmaxf(acc[mt][nt][1] + bb, 0.f));
            smw[(r + 8) * HS_STRW + cw] = pack2(fmaxf(acc[mt][nt][2] + ba, 0.f),
                                                fmaxf(acc[mt][nt][3] + bb, 0.f));
        }

    // =================== Layer 3: 16 chunks of k=32 =========================
    float acc3[2][4][4];
#pragma unroll
    for (int mt = 0; mt < 2; mt++)
#pragma unroll
        for (int nt = 0; nt < 4; nt++)
#pragma unroll
            for (int i = 0; i < 4; i++) acc3[mt][nt][i] = 0.f;

    for (int g3 = 0; g3 < 16; g3++) {
        CP_WAIT1();
        __syncthreads();  // g3==0 also publishes epilogue-2 hs writes
        prefetch_chunk(18 + g3, wtu, tid);
        const uint2* wbu = (const uint2*)(smw + HS_W + ((16 + g3) % 3) * BUF_W);
#pragma unroll
        for (int s = 0; s < 2; s++) {
            const int kw = g3 * 16 + s * 8;
            uint32_t a0[4], a1[4];
            a0[0] = smw[rA * HS_STRW + kw + tg];
            a0[1] = smw[(rA + 8) * HS_STRW + kw + tg];
            a0[2] = smw[rA * HS_STRW + kw + tg + 4];
            a0[3] = smw[(rA + 8) * HS_STRW + kw + tg + 4];
            a1[0] = smw[(rA + 16) * HS_STRW + kw + tg];
            a1[1] = smw[(rA + 24) * HS_STRW + kw + tg];
            a1[2] = smw[(rA + 16) * HS_STRW + kw + tg + 4];
            a1[3] = smw[(rA + 24) * HS_STRW + kw + tg + 4];
            const uint2* wrow = wbu + (s * 4 + tg) * 260 + wn * 32 + g;
#pragma unroll
            for (int nt = 0; nt < 4; nt++) {
                uint2 b = wrow[nt * 8];
                mma16(acc3[0][nt], a0, b.x, b.y);
                mma16(acc3[1][nt], a1, b.x, b.y);
            }
        }
    }

    // ---- epilogue 3: out = acc3 + b3 (fp32) ----
#pragma unroll
    for (int mt = 0; mt < 2; mt++)
#pragma unroll
        for (int nt = 0; nt < 4; nt++) {
            int r = wm * 32 + mt * 16 + g;
            int c = wn * 32 + nt * 8 + tg * 2;
            size_t row0 = (size_t)(ebase + r) * OUTD;
            size_t row8 = (size_t)(ebase + r + 8) * OUTD;
            float ba = b3s[c], bb = b3s[c + 1];
            out[row0 + c]     = acc3[mt][nt][0] + ba;
            out[row0 + c + 1] = acc3[mt][nt][1] + bb;
            out[row8 + c]     = acc3[mt][nt][2] + ba;
            out[row8 + c + 1] = acc3[mt][nt][3] + bb;
        }
}

// -----------------------------------------------------------------------------
extern "C" void kernel_launch(void* const* d_in, const int* in_sizes, int n_in,
                              void* d_out, int out_size) {
    const float* nf   = (const float*)d_in[0];
    const float* nh   = (const float*)d_in[1];
    const int*   src  = (const int*)d_in[2];
    const int*   dst  = (const int*)d_in[3];
    const float* dist = (const float*)d_in[4];
    const float* W1   = (const float*)d_in[5];
    const float* b1   = (const float*)d_in[6];
    const float* W2   = (const float*)d_in[7];
    const float* b2   = (const float*)d_in[8];
    const float* W3   = (const float*)d_in[9];
    const float* b3   = (const float*)d_in[10];
    float* out = (float*)d_out;

    static bool attr_set = false;
    if (!attr_set) {
        cudaFuncSetAttribute(edge_mlp_kernel,
                             cudaFuncAttributeMaxDynamicSharedMemorySize, SMEM_BYTES);
        attr_set = true;
    }
    node_pre_kernel<<<(N_NODES + 63) / 64, 512>>>(nf, nh, W1, b1);
    weight_prep_kernel<<<(128 * 512 + 128 * 256 + 255) / 256, 256>>>(W2, W3);
    edge_mlp_kernel<<<N_EDGES / 64, 512, SMEM_BYTES>>>(src, dst, dist, W1, b2, b3, out);
}